// round 8
// baseline (speedup 1.0000x reference)
#include <cuda_runtime.h>
#include <cstdint>

namespace {
constexpr int L2C   = 65536;
constexpr int NC    = 2 * L2C;      // 131072
constexpr int FINC  = 8;
constexpr int FOUTC = 8;
constexpr int KC    = 13;
constexpr int IK    = FINC * KC;    // 104
constexpr int EPB   = 32;           // edges per block
constexpr int TPB   = 256;
constexpr int CHE   = 4;            // edges per chunk
constexpr int NCH   = EPB / CHE;    // 8 chunks
constexpr int WPE   = IK * FOUTC;   // 832 mask elements per edge
constexpr int CHWRD = CHE * WPE;    // 3328 elements per chunk
constexpr int CHB_W = CHWRD * 4;    // 13312 B per chunk (word masks)
}

// x transposed to (N, FIN): one gathered column = one 32B sector.
__device__ __align__(16) float g_xt[(size_t)NC * FINC];
// 0 => 4-byte mask words ({0,1} int32 or {0,1.0f} float32); 1 => 1-byte elements
__device__ int g_mask_is_byte;

__global__ __launch_bounds__(TPB) void prep_kernel(const float* __restrict__ x,
                                                   const uint32_t* __restrict__ M) {
    if (blockIdx.x == 0 && threadIdx.x < 32) {
        int bad = 0;
        for (int i = threadIdx.x; i < 1024; i += 32) {
            uint32_t w = M[i];
            if (!(w == 0u || w == 1u || w == 0x3f800000u)) bad = 1;
        }
        bad = __any_sync(0xffffffffu, bad);
        if (threadIdx.x == 0) g_mask_is_byte = bad;
    }
    int j = blockIdx.x * blockDim.x + threadIdx.x;
    if (j >= NC) return;
    float4 a, b;
    a.x = x[0 * NC + j]; a.y = x[1 * NC + j]; a.z = x[2 * NC + j]; a.w = x[3 * NC + j];
    b.x = x[4 * NC + j]; b.y = x[5 * NC + j]; b.z = x[6 * NC + j]; b.w = x[7 * NC + j];
    float4* dst = reinterpret_cast<float4*>(g_xt) + (size_t)j * 2;
    dst[0] = a;
    dst[1] = b;
}

// ---- mbarrier + 1D bulk-TMA helpers ----
__device__ __forceinline__ void mbar_init(uint32_t mbar, uint32_t count) {
    asm volatile("mbarrier.init.shared.b64 [%0], %1;" :: "r"(mbar), "r"(count) : "memory");
}
__device__ __forceinline__ void mbar_expect_tx(uint32_t mbar, uint32_t bytes) {
    asm volatile("mbarrier.arrive.expect_tx.shared.b64 _, [%0], %1;"
                 :: "r"(mbar), "r"(bytes) : "memory");
}
__device__ __forceinline__ void mbar_wait(uint32_t mbar, uint32_t parity) {
    asm volatile(
        "{\n\t"
        ".reg .pred P;\n\t"
        "WAIT_%=:\n\t"
        "mbarrier.try_wait.parity.acquire.cta.shared::cta.b64 P, [%0], %1, 0x989680;\n\t"
        "@P bra.uni DONE_%=;\n\t"
        "bra.uni WAIT_%=;\n\t"
        "DONE_%=:\n\t"
        "}"
        :: "r"(mbar), "r"(parity) : "memory");
}
__device__ __forceinline__ void tma_1d(uint32_t dst_smem, const void* src,
                                       uint32_t bytes, uint32_t mbar) {
    asm volatile(
        "cp.async.bulk.shared::cta.global.mbarrier::complete_tx::bytes [%0], [%1], %2, [%3];"
        :: "r"(dst_smem), "l"(src), "r"(bytes), "r"(mbar) : "memory");
}

__global__ __launch_bounds__(TPB, 5) void edge_kernel(
    const float* __restrict__ Wh, const float* __restrict__ Wv,
    const float* __restrict__ bh, const float* __restrict__ bv,
    const uint8_t* __restrict__ Mh, const uint8_t* __restrict__ Mv,
    const int* __restrict__ Kh, const int* __restrict__ Kv,
    const int* __restrict__ ELh, const int* __restrict__ ELv,
    float* __restrict__ out)
{
    const bool vert = (blockIdx.y != 0);
    const float*   W    = vert ? Wv  : Wh;
    const float*   bias = vert ? bv  : bh;
    const uint8_t* M    = vert ? Mv  : Mh;
    const int*     KER  = vert ? Kv  : Kh;
    const int*     EL   = vert ? ELv : ELh;

    __shared__ __align__(128) uint32_t mbuf[2 * CHWRD];   // 26624 B raw mask ring
    __shared__ __align__(16)  float    xsf[EPB * IK];     // 13312 B
    __shared__ __align__(8)   uint64_t mbar[2];
    __shared__ int   kers[EPB * KC];
    __shared__ int   els[EPB];
    __shared__ float bsh[FOUTC];

    const int tid = threadIdx.x;
    const int e0  = blockIdx.x * EPB;

    // ---- small tables ----
    for (int t = tid; t < EPB * KC; t += TPB) kers[t] = KER[e0 * KC + t];
    if (tid < EPB)   els[tid] = EL[e0 + tid];
    if (tid < FOUTC) bsh[tid] = bias[tid];

    const uint32_t mbar0 = (uint32_t)__cvta_generic_to_shared(&mbar[0]);
    const uint32_t mbar1 = (uint32_t)__cvta_generic_to_shared(&mbar[1]);
    const uint32_t mb_s  = (uint32_t)__cvta_generic_to_shared(mbuf);

    if (tid == 0) {
        mbar_init(mbar0, 1);
        mbar_init(mbar1, 1);
        asm volatile("fence.proxy.async.shared::cta;" ::: "memory");
    }
    __syncthreads();   // mbarriers + kers visible

    // ---- roles: tid = cel<2b> | lp<6b>, lp = o*8 + ii ----
    const int cel = tid >> 6;
    const int lp  = tid & 63;
    const int o   = lp >> 3;
    const int ii  = lp & 7;

    // W row (o, ii): 13 registers
    float wreg[KC];
    #pragma unroll
    for (int k = 0; k < KC; k++) wreg[k] = W[lp * KC + k];

    const int isbyte = g_mask_is_byte;
    const uint32_t chb = isbyte ? CHWRD : CHB_W;          // bytes per chunk
    const uint8_t* Mbase = M + (size_t)e0 * WPE * (isbyte ? 1 : 4);

    // ---- kick off chunk 0 ----
    if (tid == 0) {
        mbar_expect_tx(mbar0, chb);
        tma_1d(mb_s, Mbase, chb, mbar0);
    }

    // ---- gather x once per block (overlaps chunk-0 TMA) ----
    {
        const int gel = tid >> 3, gi = tid & 7;
        #pragma unroll
        for (int k = 0; k < KC; k++) {
            int j = kers[gel * KC + k];
            xsf[gel * IK + gi * KC + k] = g_xt[(size_t)j * FINC + gi];
        }
    }
    __syncthreads();   // xsf published

    const float SCALE = (float)((2.0 + 2.0 * 2.718281828459045235) /
                                (2.718281828459045235 - 1.0));

    for (int c = 0; c < NCH; c++) {
        const int bsel = c & 1;

        // ---- producer: launch chunk c+1 into the other buffer ----
        if (c + 1 < NCH && tid == 0) {
            const uint32_t mb = (bsel ^ 1) ? mbar1 : mbar0;
            mbar_expect_tx(mb, chb);
            tma_1d(mb_s + (bsel ^ 1) * CHB_W, Mbase + (size_t)(c + 1) * chb, chb, mb);
        }

        // ---- wait for chunk c ----
        mbar_wait(bsel ? mbar1 : mbar0, (c >> 1) & 1);

        // ---- compute chunk c: thread (cel, o, ii) does 13 MACs ----
        const int eg = c * CHE + cel;
        const float* xrow = &xsf[eg * IK + ii * KC];

        float acc = 0.0f;
        if (!isbyte) {
            const uint32_t* mrow = mbuf + bsel * CHWRD + cel * WPE + lp * KC;
            #pragma unroll
            for (int k = 0; k < KC; k++)
                if (mrow[k]) acc = fmaf(wreg[k], xrow[k], acc);
        } else {
            const uint8_t* mrow = reinterpret_cast<const uint8_t*>(mbuf) +
                                  bsel * CHB_W + cel * WPE + lp * KC;
            #pragma unroll
            for (int k = 0; k < KC; k++)
                if (mrow[k]) acc = fmaf(wreg[k], xrow[k], acc);
        }

        // reduce over input features (lane bits 0..2)
        acc += __shfl_xor_sync(0xffffffffu, acc, 1);
        acc += __shfl_xor_sync(0xffffffffu, acc, 2);
        acc += __shfl_xor_sync(0xffffffffu, acc, 4);

        if (ii == 0) {
            float z = acc + bsh[o];
            float s = 1.0f / (1.0f + __expf(-z));
            out[(size_t)o * NC + els[eg]] = (s - 0.5f) * SCALE;
        }
        __syncthreads();   // all consumers done with buffer bsel -> next TMA may overwrite
    }
}

extern "C" void kernel_launch(void* const* d_in, const int* in_sizes, int n_in,
                              void* d_out, int out_size) {
    const float*   x   = (const float*)  d_in[0];
    const float*   Wh  = (const float*)  d_in[1];
    const float*   Wv  = (const float*)  d_in[2];
    const float*   bh  = (const float*)  d_in[3];
    const float*   bv  = (const float*)  d_in[4];
    const uint8_t* Mh  = (const uint8_t*)d_in[5];
    const uint8_t* Mv  = (const uint8_t*)d_in[6];
    const int*     Kh  = (const int*)    d_in[7];
    const int*     Kv  = (const int*)    d_in[8];
    const int*     ELh = (const int*)    d_in[9];
    const int*     ELv = (const int*)    d_in[10];
    float* out = (float*)d_out;

    prep_kernel<<<NC / TPB, TPB>>>(x, (const uint32_t*)Mh);

    dim3 grid(L2C / EPB, 2);   // y=0 horizontal branch, y=1 vertical
    edge_kernel<<<grid, TPB>>>(Wh, Wv, bh, bv, Mh, Mv, Kh, Kv, ELh, ELv, out);
}